// round 7
// baseline (speedup 1.0000x reference)
#include <cuda_runtime.h>

#define RWS   131072
#define KP    48
#define EPSB  1e-5f
#define SCALE 0.17677669529663687f

typedef unsigned long long ull;

// ------------------------- device scratch (no allocs) ----------------------
__device__ float g_pos[3][RWS * 256];
__device__ float g_qkvb[RWS * 768];
__device__ float g_attb[RWS * 256];
__device__ float g_partPP[2304 * 256];
__device__ float g_partP[KP * 256];
__device__ float g_mPP[2304];
__device__ float g_mP[KP];
__device__ float g_bnS[768];
__device__ float g_bnT[768];

// ------------------------- f32x2 helpers ------------------------------------
__device__ __forceinline__ void ffma2(ull &d, ull a, ull b) {
    asm("fma.rn.f32x2 %0, %1, %2, %3;" : "=l"(d) : "l"(a), "l"(b), "l"(d));
}
__device__ __forceinline__ ull pack2(float x, float y) {
    ull r; asm("mov.b64 %0, {%1, %2};" : "=l"(r) : "f"(x), "f"(y)); return r;
}
__device__ __forceinline__ float2 unpack2(ull v) {
    float2 f; asm("mov.b64 {%0, %1}, %2;" : "=f"(f.x), "=f"(f.y) : "l"(v)); return f;
}

// ------------------------- K1: partial pos stats ----------------------------
__global__ __launch_bounds__(256) void stats1_kernel(const float* __restrict__ pr) {
    __shared__ float Ps[64 * KP];
    int t = threadIdx.x, bid = blockIdx.x;
    float accPP[9];
#pragma unroll
    for (int i = 0; i < 9; i++) accPP[i] = 0.f;
    float accP = 0.f;

    for (int ch = 0; ch < 8; ch++) {
        long r0 = (long)bid * 512 + ch * 64;
        const float4* src = (const float4*)(pr + r0 * KP);
        float4* d4 = (float4*)Ps;
#pragma unroll
        for (int i = 0; i < 3; i++) d4[i * 256 + t] = src[i * 256 + t];
        __syncthreads();
#pragma unroll
        for (int i = 0; i < 9; i++) {
            int pair = t * 9 + i;
            int a = pair / KP, b = pair % KP;
            float s = 0.f;
#pragma unroll 8
            for (int r = 0; r < 64; r++) s += Ps[r * KP + a] * Ps[r * KP + b];
            accPP[i] += s;
        }
        if (t < KP) {
            float s = 0.f;
#pragma unroll 8
            for (int r = 0; r < 64; r++) s += Ps[r * KP + t];
            accP += s;
        }
        __syncthreads();
    }
#pragma unroll
    for (int i = 0; i < 9; i++) g_partPP[(t * 9 + i) * 256 + bid] = accPP[i];
    if (t < KP) g_partP[t * 256 + bid] = accP;
}

// ------------------------- K2: reduce partials ------------------------------
__global__ __launch_bounds__(256) void stats2_kernel() {
    int idx = blockIdx.x * 256 + threadIdx.x;
    const float invR = 1.f / (float)RWS;
    if (idx < 2304) {
        float s = 0.f;
        for (int j = 0; j < 256; j++) s += g_partPP[idx * 256 + j];
        g_mPP[idx] = s * invR;
    } else if (idx < 2304 + KP) {
        int k = idx - 2304;
        float s = 0.f;
        for (int j = 0; j < 256; j++) s += g_partP[k * 256 + j];
        g_mP[k] = s * invR;
    }
}

// ------------------------- K3: analytic BN fold -----------------------------
__global__ __launch_bounds__(768) void bnfin_kernel(
    const float* qw1, const float* qg, const float* qbe,
    const float* kw1, const float* kg, const float* kbe,
    const float* vw1, const float* vg, const float* vbe)
{
    __shared__ float sPP[2304];
    __shared__ float sP[KP];
    int t = threadIdx.x;
    for (int i = t; i < 2304; i += 768) sPP[i] = g_mPP[i];
    if (t < KP) sP[t] = g_mP[t];
    __syncthreads();

    int p = t >> 8, c = t & 255;
    const float* w1 = (p == 0) ? qw1 : (p == 1) ? kw1 : vw1;
    const float* gg = (p == 0) ? qg  : (p == 1) ? kg  : vg;
    const float* be = (p == 0) ? qbe : (p == 1) ? kbe : vbe;

    float w[KP];
#pragma unroll
    for (int j = 0; j < KP; j++) w[j] = w1[c * KP + j];
    float dm = 0.f;
#pragma unroll
    for (int j = 0; j < KP; j++) dm += w[j] * sP[j];
    float q2 = 0.f;
    for (int i = 0; i < KP; i++) {
        float s = 0.f;
#pragma unroll 8
        for (int j = 0; j < KP; j++) s += w[j] * sPP[i * KP + j];
        q2 += w[i] * s;
    }
    float var = q2 - dm * dm;
    float S = gg[c] * rsqrtf(var + EPSB);
    g_bnS[t] = S;
    g_bnT[t] = be[c] - dm * S;
}

// ------------------------- K4: fused pos-MLP --------------------------------
#define SMEM_MLP 126976
__global__ __launch_bounds__(256) void mlp_kernel(
    const float* __restrict__ pr,
    const float* qw1, const float* kw1, const float* vw1,
    const float* qw2, const float* kw2, const float* vw2,
    const float* qb2, const float* kb2, const float* vb2)
{
    extern __shared__ float sm[];
    float* Hs  = sm;                 // 64*256
    float* Ps  = sm + 16384;         // 64*48
    float* W1T = Ps + 64 * KP;       // 48*256
    float* W2s = sm + 16384;         // 32*256 (reuse after stage A)

    int t = threadIdx.x;
    int p = blockIdx.y;
    long rowBase = (long)blockIdx.x * 64;
    const float* W1 = (p == 0) ? qw1 : (p == 1) ? kw1 : vw1;
    const float* W2 = (p == 0) ? qw2 : (p == 1) ? kw2 : vw2;
    const float* B2 = (p == 0) ? qb2 : (p == 1) ? kb2 : vb2;

    {
        const float4* src = (const float4*)(pr + rowBase * KP);
        float4* d4 = (float4*)Ps;
#pragma unroll
        for (int i = 0; i < 3; i++) d4[i * 256 + t] = src[i * 256 + t];
        const float4* wsrc = (const float4*)(W1 + t * KP);
#pragma unroll
        for (int i = 0; i < 12; i++) {
            float4 w4 = wsrc[i];
            W1T[(i * 4 + 0) * 256 + t] = w4.x;
            W1T[(i * 4 + 1) * 256 + t] = w4.y;
            W1T[(i * 4 + 2) * 256 + t] = w4.z;
            W1T[(i * 4 + 3) * 256 + t] = w4.w;
        }
    }
    __syncthreads();

    int tr = t >> 5, tc = t & 31;

    // stage A: h = (pos @ W1^T)
    ull acc[8][4];
#pragma unroll
    for (int i = 0; i < 8; i++)
#pragma unroll
        for (int j = 0; j < 4; j++) acc[i][j] = 0ull;

    for (int k0 = 0; k0 < KP; k0 += 4) {
        float4 a4[8];
#pragma unroll
        for (int i = 0; i < 8; i++)
            a4[i] = *(const float4*)&Ps[(tr * 8 + i) * KP + k0];
#pragma unroll
        for (int jj = 0; jj < 4; jj++) {
            int k = k0 + jj;
            ulonglong2 b01 = *(const ulonglong2*)&W1T[k * 256 + tc * 8];
            ulonglong2 b23 = *(const ulonglong2*)&W1T[k * 256 + tc * 8 + 4];
#pragma unroll
            for (int i = 0; i < 8; i++) {
                float a = ((const float*)&a4[i])[jj];
                ull a2 = pack2(a, a);
                ffma2(acc[i][0], a2, b01.x);
                ffma2(acc[i][1], a2, b01.y);
                ffma2(acc[i][2], a2, b23.x);
                ffma2(acc[i][3], a2, b23.y);
            }
        }
    }

    // BN fold + relu -> Hs
    {
        float4 s0 = *(const float4*)&g_bnS[p * 256 + tc * 8];
        float4 s1 = *(const float4*)&g_bnS[p * 256 + tc * 8 + 4];
        float4 t0 = *(const float4*)&g_bnT[p * 256 + tc * 8];
        float4 t1 = *(const float4*)&g_bnT[p * 256 + tc * 8 + 4];
        float Sv[8] = {s0.x, s0.y, s0.z, s0.w, s1.x, s1.y, s1.z, s1.w};
        float Tv[8] = {t0.x, t0.y, t0.z, t0.w, t1.x, t1.y, t1.z, t1.w};
#pragma unroll
        for (int i = 0; i < 8; i++) {
            float h[8];
#pragma unroll
            for (int j = 0; j < 4; j++) {
                float2 f = unpack2(acc[i][j]);
                h[2 * j] = f.x; h[2 * j + 1] = f.y;
            }
#pragma unroll
            for (int j = 0; j < 8; j++) h[j] = fmaxf(fmaf(h[j], Sv[j], Tv[j]), 0.f);
            *(float4*)&Hs[(tr * 8 + i) * 256 + tc * 8]     = make_float4(h[0], h[1], h[2], h[3]);
            *(float4*)&Hs[(tr * 8 + i) * 256 + tc * 8 + 4] = make_float4(h[4], h[5], h[6], h[7]);
        }
    }

    // stage B: out = h @ W2^T + b2
    ull ac2[8][4];
#pragma unroll
    for (int i = 0; i < 8; i++)
#pragma unroll
        for (int j = 0; j < 4; j++) ac2[i][j] = 0ull;

    for (int kc = 0; kc < 256; kc += 32) {
        __syncthreads();
        {
            const float4* wsrc = (const float4*)(W2 + (long)t * 256 + kc);
#pragma unroll
            for (int i = 0; i < 8; i++) {
                float4 w4 = wsrc[i];
                W2s[(i * 4 + 0) * 256 + t] = w4.x;
                W2s[(i * 4 + 1) * 256 + t] = w4.y;
                W2s[(i * 4 + 2) * 256 + t] = w4.z;
                W2s[(i * 4 + 3) * 256 + t] = w4.w;
            }
        }
        __syncthreads();
        for (int k0 = 0; k0 < 32; k0 += 4) {
            float4 a4[8];
#pragma unroll
            for (int i = 0; i < 8; i++)
                a4[i] = *(const float4*)&Hs[(tr * 8 + i) * 256 + kc + k0];
#pragma unroll
            for (int jj = 0; jj < 4; jj++) {
                int kk = k0 + jj;
                ulonglong2 b01 = *(const ulonglong2*)&W2s[kk * 256 + tc * 8];
                ulonglong2 b23 = *(const ulonglong2*)&W2s[kk * 256 + tc * 8 + 4];
#pragma unroll
                for (int i = 0; i < 8; i++) {
                    float a = ((const float*)&a4[i])[jj];
                    ull a2 = pack2(a, a);
                    ffma2(ac2[i][0], a2, b01.x);
                    ffma2(ac2[i][1], a2, b01.y);
                    ffma2(ac2[i][2], a2, b23.x);
                    ffma2(ac2[i][3], a2, b23.y);
                }
            }
        }
    }

    {
        float4 bb0 = *(const float4*)&B2[tc * 8];
        float4 bb1 = *(const float4*)&B2[tc * 8 + 4];
        float bv[8] = {bb0.x, bb0.y, bb0.z, bb0.w, bb1.x, bb1.y, bb1.z, bb1.w};
        float* outp = &g_pos[p][0];
#pragma unroll
        for (int i = 0; i < 8; i++) {
            float h[8];
#pragma unroll
            for (int j = 0; j < 4; j++) {
                float2 f = unpack2(ac2[i][j]);
                h[2 * j] = f.x + bv[2 * j];
                h[2 * j + 1] = f.y + bv[2 * j + 1];
            }
            long ro = (rowBase + tr * 8 + i) * 256 + tc * 8;
            *(float4*)&outp[ro]     = make_float4(h[0], h[1], h[2], h[3]);
            *(float4*)&outp[ro + 4] = make_float4(h[4], h[5], h[6], h[7]);
        }
    }
}

// ------------------------- K5: generic GEMM C = A @ W^T (+bias) -------------
#define SMEM_GEMM 98304
__global__ __launch_bounds__(256) void gemm_kernel(
    const float* __restrict__ A, const float* __restrict__ W,
    const float* __restrict__ bias, float* __restrict__ C, int ldc)
{
    extern __shared__ float sm[];
    float* As = sm;           // 64*256
    float* Ws = sm + 16384;   // 32*256

    int t = threadIdx.x;
    long rowBase = (long)blockIdx.x * 64;
    int colBase = blockIdx.y * 256;
    const float* Wp = W + (long)colBase * 256;

    {
        const float4* src = (const float4*)(A + rowBase * 256);
        float4* d4 = (float4*)As;
#pragma unroll
        for (int i = 0; i < 16; i++) d4[i * 256 + t] = src[i * 256 + t];
    }

    int tr = t >> 5, tc = t & 31;
    ull acc[8][4];
#pragma unroll
    for (int i = 0; i < 8; i++)
#pragma unroll
        for (int j = 0; j < 4; j++) acc[i][j] = 0ull;

    for (int kc = 0; kc < 256; kc += 32) {
        __syncthreads();
        {
            const float4* wsrc = (const float4*)(Wp + (long)t * 256 + kc);
#pragma unroll
            for (int i = 0; i < 8; i++) {
                float4 w4 = wsrc[i];
                Ws[(i * 4 + 0) * 256 + t] = w4.x;
                Ws[(i * 4 + 1) * 256 + t] = w4.y;
                Ws[(i * 4 + 2) * 256 + t] = w4.z;
                Ws[(i * 4 + 3) * 256 + t] = w4.w;
            }
        }
        __syncthreads();
        for (int k0 = 0; k0 < 32; k0 += 4) {
            float4 a4[8];
#pragma unroll
            for (int i = 0; i < 8; i++)
                a4[i] = *(const float4*)&As[(tr * 8 + i) * 256 + kc + k0];
#pragma unroll
            for (int jj = 0; jj < 4; jj++) {
                int kk = k0 + jj;
                ulonglong2 b01 = *(const ulonglong2*)&Ws[kk * 256 + tc * 8];
                ulonglong2 b23 = *(const ulonglong2*)&Ws[kk * 256 + tc * 8 + 4];
#pragma unroll
                for (int i = 0; i < 8; i++) {
                    float a = ((const float*)&a4[i])[jj];
                    ull a2 = pack2(a, a);
                    ffma2(acc[i][0], a2, b01.x);
                    ffma2(acc[i][1], a2, b01.y);
                    ffma2(acc[i][2], a2, b23.x);
                    ffma2(acc[i][3], a2, b23.y);
                }
            }
        }
    }

    float bv[8];
    if (bias) {
        float4 bb0 = *(const float4*)&bias[colBase + tc * 8];
        float4 bb1 = *(const float4*)&bias[colBase + tc * 8 + 4];
        bv[0]=bb0.x; bv[1]=bb0.y; bv[2]=bb0.z; bv[3]=bb0.w;
        bv[4]=bb1.x; bv[5]=bb1.y; bv[6]=bb1.z; bv[7]=bb1.w;
    } else {
#pragma unroll
        for (int j = 0; j < 8; j++) bv[j] = 0.f;
    }
#pragma unroll
    for (int i = 0; i < 8; i++) {
        float h[8];
#pragma unroll
        for (int j = 0; j < 4; j++) {
            float2 f = unpack2(acc[i][j]);
            h[2 * j] = f.x + bv[2 * j];
            h[2 * j + 1] = f.y + bv[2 * j + 1];
        }
        long ro = (rowBase + tr * 8 + i) * (long)ldc + colBase + tc * 8;
        *(float4*)&C[ro]     = make_float4(h[0], h[1], h[2], h[3]);
        *(float4*)&C[ro + 4] = make_float4(h[4], h[5], h[6], h[7]);
    }
}

// ------------------------- K6: attention ------------------------------------
// padded strides to kill bank conflicts
#define STA 66
#define STV 34
#define STT 17
#define SMEM_ATT ((8*16*STA*2 + 8*16*STV + 8*16*STT) * 4)
__global__ __launch_bounds__(256) void attn_kernel() {
    extern __shared__ float sm[];
    float* sA  = sm;                       // [h*16+n][66]  (q | k)
    float* sB  = sA + 8 * 16 * STA;        // [h*16+m][66]  (k+pq | pk)
    float* sV  = sB + 8 * 16 * STA;        // [h*16+m][34]  (v+pv)
    float* sAt = sV + 8 * 16 * STV;        // [h*16+n][17]

    int t = threadIdx.x;
    long rb = (long)blockIdx.x * 16;
    const float* qkv = g_qkvb + rb * 768;
    const float* pq = &g_pos[0][rb * 256];
    const float* pk = &g_pos[1][rb * 256];
    const float* pv = &g_pos[2][rb * 256];

#pragma unroll
    for (int it = 0; it < 4; it++) {
        int u = it * 256 + t;          // 0..1023
        int n = u >> 6;
        int c = (u & 63) * 4;
        int h = c >> 5, d = c & 31;
        float4 q4  = *(const float4*)&qkv[n * 768 + c];
        float4 k4  = *(const float4*)&qkv[n * 768 + 256 + c];
        float4 v4  = *(const float4*)&qkv[n * 768 + 512 + c];
        float4 pq4 = *(const float4*)&pq[n * 256 + c];
        float4 pk4 = *(const float4*)&pk[n * 256 + c];
        float4 pv4 = *(const float4*)&pv[n * 256 + c];
        int ba = (h * 16 + n) * STA;
        *(float2*)&sA[ba + d]          = make_float2(q4.x, q4.y);
        *(float2*)&sA[ba + d + 2]      = make_float2(q4.z, q4.w);
        *(float2*)&sA[ba + 32 + d]     = make_float2(k4.x, k4.y);
        *(float2*)&sA[ba + 32 + d + 2] = make_float2(k4.z, k4.w);
        *(float2*)&sB[ba + d]          = make_float2(k4.x + pq4.x, k4.y + pq4.y);
        *(float2*)&sB[ba + d + 2]      = make_float2(k4.z + pq4.z, k4.w + pq4.w);
        *(float2*)&sB[ba + 32 + d]     = make_float2(pk4.x, pk4.y);
        *(float2*)&sB[ba + 32 + d + 2] = make_float2(pk4.z, pk4.w);
        int bv = (h * 16 + n) * STV;
        *(float2*)&sV[bv + d]          = make_float2(v4.x + pv4.x, v4.y + pv4.y);
        *(float2*)&sV[bv + d + 2]      = make_float2(v4.z + pv4.z, v4.w + pv4.w);
    }
    __syncthreads();

    int h = t >> 5, l = t & 31;
    int n = l >> 1;
    int mb = (l & 1) * 8;

    // dots: 8 (n,m) pairs per lane, length-64 dot via f32x2
    ull acc2[8];
#pragma unroll
    for (int j = 0; j < 8; j++) acc2[j] = 0ull;
    const ull* Ar = (const ull*)&sA[(h * 16 + n) * STA];
    const ull* Br[8];
#pragma unroll
    for (int j = 0; j < 8; j++) Br[j] = (const ull*)&sB[(h * 16 + mb + j) * STA];
#pragma unroll 8
    for (int d2 = 0; d2 < 32; d2++) {
        ull a2 = Ar[d2];
#pragma unroll
        for (int j = 0; j < 8; j++) ffma2(acc2[j], a2, Br[j][d2]);
    }
    float dots[8];
#pragma unroll
    for (int j = 0; j < 8; j++) {
        float2 f = unpack2(acc2[j]);
        dots[j] = (f.x + f.y) * SCALE;
    }

    // softmax across 16 m (partner lane l^1 holds the other 8)
    float mx = dots[0];
#pragma unroll
    for (int j = 1; j < 8; j++) mx = fmaxf(mx, dots[j]);
    mx = fmaxf(mx, __shfl_xor_sync(0xFFFFFFFFu, mx, 1));
    float ssum = 0.f, e[8];
#pragma unroll
    for (int j = 0; j < 8; j++) { e[j] = __expf(dots[j] - mx); ssum += e[j]; }
    ssum += __shfl_xor_sync(0xFFFFFFFFu, ssum, 1);
    float inv = 1.f / ssum;
#pragma unroll
    for (int j = 0; j < 8; j++) sAt[(h * 16 + n) * STT + mb + j] = e[j] * inv;
    __syncwarp();

    // out[n][d] = sum_m attn[n][m] * Vp[m][d]; lane owns 16 d's
    int dh = (l & 1) * 16;
    ull o2[8];
#pragma unroll
    for (int j = 0; j < 8; j++) o2[j] = 0ull;
    const float* At = &sAt[(h * 16 + n) * STT];
#pragma unroll
    for (int m = 0; m < 16; m++) {
        float a = At[m];
        ull a2 = pack2(a, a);
        const ull* Vr = (const ull*)&sV[(h * 16 + m) * STV + dh];
#pragma unroll
        for (int dp = 0; dp < 8; dp++) ffma2(o2[dp], a2, Vr[dp]);
    }
    float* op = g_attb + (rb + n) * 256 + h * 32 + dh;
#pragma unroll
    for (int dp = 0; dp < 8; dp++) {
        float2 f = unpack2(o2[dp]);
        *(float2*)&op[2 * dp] = f;
    }
}

// ------------------------- host launcher ------------------------------------
extern "C" void kernel_launch(void* const* d_in, const int* in_sizes, int n_in,
                              void* d_out, int out_size) {
    const float* x      = (const float*)d_in[0];
    const float* pr     = (const float*)d_in[1];
    const float* qkv_w  = (const float*)d_in[2];
    const float* proj_w = (const float*)d_in[3];
    const float* proj_b = (const float*)d_in[4];
    const float* q_w1 = (const float*)d_in[5];
    const float* q_g  = (const float*)d_in[7];
    const float* q_be = (const float*)d_in[8];
    const float* q_w2 = (const float*)d_in[9];
    const float* q_b2 = (const float*)d_in[10];
    const float* k_w1 = (const float*)d_in[11];
    const float* k_g  = (const float*)d_in[13];
    const float* k_be = (const float*)d_in[14];
    const float* k_w2 = (const float*)d_in[15];
    const float* k_b2 = (const float*)d_in[16];
    const float* v_w1 = (const float*)d_in[17];
    const float* v_g  = (const float*)d_in[19];
    const float* v_be = (const float*)d_in[20];
    const float* v_w2 = (const float*)d_in[21];
    const float* v_b2 = (const float*)d_in[22];
    float* out = (float*)d_out;

    cudaFuncSetAttribute(mlp_kernel,  cudaFuncAttributeMaxDynamicSharedMemorySize, SMEM_MLP);
    cudaFuncSetAttribute(gemm_kernel, cudaFuncAttributeMaxDynamicSharedMemorySize, SMEM_GEMM);
    cudaFuncSetAttribute(attn_kernel, cudaFuncAttributeMaxDynamicSharedMemorySize, SMEM_ATT);

    void *p_qkvb = nullptr, *p_attb = nullptr;
    cudaGetSymbolAddress(&p_qkvb, g_qkvb);
    cudaGetSymbolAddress(&p_attb, g_attb);

    stats1_kernel<<<256, 256>>>(pr);
    stats2_kernel<<<10, 256>>>();
    bnfin_kernel<<<1, 768>>>(q_w1, q_g, q_be, k_w1, k_g, k_be, v_w1, v_g, v_be);
    gemm_kernel<<<dim3(2048, 3), 256, SMEM_GEMM>>>(x, qkv_w, nullptr, (float*)p_qkvb, 768);
    mlp_kernel<<<dim3(2048, 3), 256, SMEM_MLP>>>(pr, q_w1, k_w1, v_w1,
                                                 q_w2, k_w2, v_w2,
                                                 q_b2, k_b2, v_b2);
    attn_kernel<<<8192, 256, SMEM_ATT>>>();
    gemm_kernel<<<dim3(2048, 1), 256, SMEM_GEMM>>>((const float*)p_attb, proj_w, proj_b, out, 256);
}

// round 8
// speedup vs baseline: 1.0369x; 1.0369x over previous
#include <cuda_runtime.h>

#define RWS   131072
#define KP    48
#define EPSB  1e-5f
#define SCALE 0.17677669529663687f

typedef unsigned long long ull;

// ------------------------- device scratch (no allocs) ----------------------
__device__ float g_pos[3][RWS * 256];
__device__ float g_hbuf[3][RWS * 256];
__device__ float g_qkvb[RWS * 768];
__device__ float g_attb[RWS * 256];
__device__ float g_partPP[2304 * 256];
__device__ float g_partP[KP * 256];
__device__ float g_mPP[2304];
__device__ float g_mP[KP];
__device__ float g_bnS[768];
__device__ float g_bnT[768];

// ------------------------- f32x2 helpers ------------------------------------
__device__ __forceinline__ void ffma2(ull &d, ull a, ull b) {
    asm("fma.rn.f32x2 %0, %1, %2, %3;" : "=l"(d) : "l"(a), "l"(b), "l"(d));
}
__device__ __forceinline__ ull pack2(float x, float y) {
    ull r; asm("mov.b64 %0, {%1, %2};" : "=l"(r) : "f"(x), "f"(y)); return r;
}
__device__ __forceinline__ float2 unpack2(ull v) {
    float2 f; asm("mov.b64 {%0, %1}, %2;" : "=f"(f.x), "=f"(f.y) : "l"(v)); return f;
}

// ------------------------- K1: partial pos stats ----------------------------
__global__ __launch_bounds__(256) void stats1_kernel(const float* __restrict__ pr) {
    __shared__ float Ps[64 * KP];
    int t = threadIdx.x, bid = blockIdx.x;
    float accPP[9];
#pragma unroll
    for (int i = 0; i < 9; i++) accPP[i] = 0.f;
    float accP = 0.f;

    for (int ch = 0; ch < 8; ch++) {
        long r0 = (long)bid * 512 + ch * 64;
        const float4* src = (const float4*)(pr + r0 * KP);
        float4* d4 = (float4*)Ps;
#pragma unroll
        for (int i = 0; i < 3; i++) d4[i * 256 + t] = src[i * 256 + t];
        __syncthreads();
#pragma unroll
        for (int i = 0; i < 9; i++) {
            int pair = t * 9 + i;
            int a = pair / KP, b = pair % KP;
            float s = 0.f;
#pragma unroll 8
            for (int r = 0; r < 64; r++) s += Ps[r * KP + a] * Ps[r * KP + b];
            accPP[i] += s;
        }
        if (t < KP) {
            float s = 0.f;
#pragma unroll 8
            for (int r = 0; r < 64; r++) s += Ps[r * KP + t];
            accP += s;
        }
        __syncthreads();
    }
#pragma unroll
    for (int i = 0; i < 9; i++) g_partPP[(t * 9 + i) * 256 + bid] = accPP[i];
    if (t < KP) g_partP[t * 256 + bid] = accP;
}

// ------------------------- K2: reduce partials ------------------------------
__global__ __launch_bounds__(256) void stats2_kernel() {
    int idx = blockIdx.x * 256 + threadIdx.x;
    const float invR = 1.f / (float)RWS;
    if (idx < 2304) {
        float s = 0.f;
        for (int j = 0; j < 256; j++) s += g_partPP[idx * 256 + j];
        g_mPP[idx] = s * invR;
    } else if (idx < 2304 + KP) {
        int k = idx - 2304;
        float s = 0.f;
        for (int j = 0; j < 256; j++) s += g_partP[k * 256 + j];
        g_mP[k] = s * invR;
    }
}

// ------------------------- K3: analytic BN fold -----------------------------
__global__ __launch_bounds__(768) void bnfin_kernel(
    const float* qw1, const float* qg, const float* qbe,
    const float* kw1, const float* kg, const float* kbe,
    const float* vw1, const float* vg, const float* vbe)
{
    __shared__ float sPP[2304];
    __shared__ float sP[KP];
    int t = threadIdx.x;
    for (int i = t; i < 2304; i += 768) sPP[i] = g_mPP[i];
    if (t < KP) sP[t] = g_mP[t];
    __syncthreads();

    int p = t >> 8, c = t & 255;
    const float* w1 = (p == 0) ? qw1 : (p == 1) ? kw1 : vw1;
    const float* gg = (p == 0) ? qg  : (p == 1) ? kg  : vg;
    const float* be = (p == 0) ? qbe : (p == 1) ? kbe : vbe;

    float w[KP];
#pragma unroll
    for (int j = 0; j < KP; j++) w[j] = w1[c * KP + j];
    float dm = 0.f;
#pragma unroll
    for (int j = 0; j < KP; j++) dm += w[j] * sP[j];
    float q2 = 0.f;
    for (int i = 0; i < KP; i++) {
        float s = 0.f;
#pragma unroll 8
        for (int j = 0; j < KP; j++) s += w[j] * sPP[i * KP + j];
        q2 += w[i] * s;
    }
    float var = q2 - dm * dm;
    float S = gg[c] * rsqrtf(var + EPSB);
    g_bnS[t] = S;
    g_bnT[t] = be[c] - dm * S;
}

// ------------------------- K4: pos-MLP stage A (K=48, BN+relu) --------------
// tile 64 rows x 256 cols, 256 thr, 8x8/thread, conflict-free column split
#define SMEM_MLPA 61440
__global__ __launch_bounds__(256, 2) void mlpA_kernel(
    const float* __restrict__ pr,
    const float* qw1, const float* kw1, const float* vw1)
{
    extern __shared__ float sm[];
    float* Ps  = sm;               // 64*48
    float* W1T = sm + 64 * KP;     // 48*256

    int t = threadIdx.x;
    int p = blockIdx.y;
    long rowBase = (long)blockIdx.x * 64;
    const float* W1 = (p == 0) ? qw1 : (p == 1) ? kw1 : vw1;

    {
        const float4* src = (const float4*)(pr + rowBase * KP);
        float4* d4 = (float4*)Ps;
#pragma unroll
        for (int i = 0; i < 3; i++) d4[i * 256 + t] = src[i * 256 + t];
        const float4* wsrc = (const float4*)(W1 + t * KP);
#pragma unroll
        for (int i = 0; i < 12; i++) {
            float4 w4 = wsrc[i];
            W1T[(i * 4 + 0) * 256 + t] = w4.x;
            W1T[(i * 4 + 1) * 256 + t] = w4.y;
            W1T[(i * 4 + 2) * 256 + t] = w4.z;
            W1T[(i * 4 + 3) * 256 + t] = w4.w;
        }
    }
    __syncthreads();

    int tr = t >> 5, tc = t & 31;
    ull acc[8][4];
#pragma unroll
    for (int i = 0; i < 8; i++)
#pragma unroll
        for (int j = 0; j < 4; j++) acc[i][j] = 0ull;

    for (int k0 = 0; k0 < KP; k0 += 4) {
        float4 a4[8];
#pragma unroll
        for (int i = 0; i < 8; i++)
            a4[i] = *(const float4*)&Ps[(tr * 8 + i) * KP + k0];
#pragma unroll
        for (int jj = 0; jj < 4; jj++) {
            int k = k0 + jj;
            ulonglong2 blo = *(const ulonglong2*)&W1T[k * 256 + tc * 4];
            ulonglong2 bhi = *(const ulonglong2*)&W1T[k * 256 + 128 + tc * 4];
#pragma unroll
            for (int i = 0; i < 8; i++) {
                float a = ((const float*)&a4[i])[jj];
                ull a2 = pack2(a, a);
                ffma2(acc[i][0], a2, blo.x);
                ffma2(acc[i][1], a2, blo.y);
                ffma2(acc[i][2], a2, bhi.x);
                ffma2(acc[i][3], a2, bhi.y);
            }
        }
    }

    // BN fold + relu -> g_hbuf[p]
    {
        float4 s0 = *(const float4*)&g_bnS[p * 256 + tc * 4];
        float4 s1 = *(const float4*)&g_bnS[p * 256 + 128 + tc * 4];
        float4 t0 = *(const float4*)&g_bnT[p * 256 + tc * 4];
        float4 t1 = *(const float4*)&g_bnT[p * 256 + 128 + tc * 4];
        float Sv[8] = {s0.x, s0.y, s0.z, s0.w, s1.x, s1.y, s1.z, s1.w};
        float Tv[8] = {t0.x, t0.y, t0.z, t0.w, t1.x, t1.y, t1.z, t1.w};
        float* outp = &g_hbuf[p][0];
#pragma unroll
        for (int i = 0; i < 8; i++) {
            float h[8];
#pragma unroll
            for (int j = 0; j < 4; j++) {
                float2 f = unpack2(acc[i][j]);
                h[2 * j] = f.x; h[2 * j + 1] = f.y;
            }
#pragma unroll
            for (int j = 0; j < 8; j++) h[j] = fmaxf(fmaf(h[j], Sv[j], Tv[j]), 0.f);
            long ro = (rowBase + tr * 8 + i) * 256;
            *(float4*)&outp[ro + tc * 4]       = make_float4(h[0], h[1], h[2], h[3]);
            *(float4*)&outp[ro + 128 + tc * 4] = make_float4(h[4], h[5], h[6], h[7]);
        }
    }
}

// ------------------------- K5: generic GEMM C = A @ W^T (+bias) -------------
// 64x256 tile, K=256 in 32-k chunks, conflict-free B loads, padded A stage
#define ASTRIDE 36
#define SMEM_GEMM ((64 * ASTRIDE + 32 * 256) * 4)
__global__ __launch_bounds__(256, 2) void gemm_kernel(
    const float* __restrict__ A, const float* __restrict__ W,
    const float* __restrict__ bias, float* __restrict__ C, int ldc)
{
    extern __shared__ float sm[];
    float* As = sm;                     // 64 x 36 (padded)
    float* Ws = sm + 64 * ASTRIDE;      // 32 x 256

    int t = threadIdx.x;
    long rowBase = (long)blockIdx.x * 64;
    int colBase = blockIdx.y * 256;
    const float* Wp = W + (long)colBase * 256;

    int tr = t >> 5, tc = t & 31;
    ull acc[8][4];
#pragma unroll
    for (int i = 0; i < 8; i++)
#pragma unroll
        for (int j = 0; j < 4; j++) acc[i][j] = 0ull;

    for (int kc = 0; kc < 256; kc += 32) {
        __syncthreads();
        // stage A chunk (64 x 32)
#pragma unroll
        for (int i = 0; i < 2; i++) {
            int idx = t * 2 + i;
            int r = idx >> 3, c4 = idx & 7;
            float4 a = *(const float4*)&A[(rowBase + r) * 256 + kc + c4 * 4];
            *(float4*)&As[r * ASTRIDE + c4 * 4] = a;
        }
        // stage W chunk transposed (32 x 256)
        {
            const float4* wsrc = (const float4*)(Wp + (long)t * 256 + kc);
#pragma unroll
            for (int i = 0; i < 8; i++) {
                float4 w4 = wsrc[i];
                Ws[(i * 4 + 0) * 256 + t] = w4.x;
                Ws[(i * 4 + 1) * 256 + t] = w4.y;
                Ws[(i * 4 + 2) * 256 + t] = w4.z;
                Ws[(i * 4 + 3) * 256 + t] = w4.w;
            }
        }
        __syncthreads();
        for (int k0 = 0; k0 < 32; k0 += 4) {
            float4 a4[8];
#pragma unroll
            for (int i = 0; i < 8; i++)
                a4[i] = *(const float4*)&As[(tr * 8 + i) * ASTRIDE + k0];
#pragma unroll
            for (int jj = 0; jj < 4; jj++) {
                int kk = k0 + jj;
                ulonglong2 blo = *(const ulonglong2*)&Ws[kk * 256 + tc * 4];
                ulonglong2 bhi = *(const ulonglong2*)&Ws[kk * 256 + 128 + tc * 4];
#pragma unroll
                for (int i = 0; i < 8; i++) {
                    float a = ((const float*)&a4[i])[jj];
                    ull a2 = pack2(a, a);
                    ffma2(acc[i][0], a2, blo.x);
                    ffma2(acc[i][1], a2, blo.y);
                    ffma2(acc[i][2], a2, bhi.x);
                    ffma2(acc[i][3], a2, bhi.y);
                }
            }
        }
    }

    float bv[8];
    if (bias) {
        float4 b0 = *(const float4*)&bias[colBase + tc * 4];
        float4 b1 = *(const float4*)&bias[colBase + 128 + tc * 4];
        bv[0]=b0.x; bv[1]=b0.y; bv[2]=b0.z; bv[3]=b0.w;
        bv[4]=b1.x; bv[5]=b1.y; bv[6]=b1.z; bv[7]=b1.w;
    } else {
#pragma unroll
        for (int j = 0; j < 8; j++) bv[j] = 0.f;
    }
#pragma unroll
    for (int i = 0; i < 8; i++) {
        float h[8];
#pragma unroll
        for (int j = 0; j < 4; j++) {
            float2 f = unpack2(acc[i][j]);
            h[2 * j] = f.x + bv[2 * j];
            h[2 * j + 1] = f.y + bv[2 * j + 1];
        }
        long ro = (rowBase + tr * 8 + i) * (long)ldc + colBase;
        *(float4*)&C[ro + tc * 4]       = make_float4(h[0], h[1], h[2], h[3]);
        *(float4*)&C[ro + 128 + tc * 4] = make_float4(h[4], h[5], h[6], h[7]);
    }
}

// ------------------------- K6: attention ------------------------------------
#define STA 66
#define STV 34
#define STT 17
#define SMEM_ATT ((8*16*STA*2 + 8*16*STV + 8*16*STT) * 4)
__global__ __launch_bounds__(256) void attn_kernel() {
    extern __shared__ float sm[];
    float* sA  = sm;                       // [h*16+n][66]  (q | k)
    float* sB  = sA + 8 * 16 * STA;        // [h*16+m][66]  (k+pq | pk)
    float* sV  = sB + 8 * 16 * STA;        // [h*16+m][34]  (v+pv)
    float* sAt = sV + 8 * 16 * STV;        // [h*16+n][17]

    int t = threadIdx.x;
    long rb = (long)blockIdx.x * 16;
    const float* qkv = g_qkvb + rb * 768;
    const float* pq = &g_pos[0][rb * 256];
    const float* pk = &g_pos[1][rb * 256];
    const float* pv = &g_pos[2][rb * 256];

#pragma unroll
    for (int it = 0; it < 4; it++) {
        int u = it * 256 + t;
        int n = u >> 6;
        int c = (u & 63) * 4;
        int h = c >> 5, d = c & 31;
        float4 q4  = *(const float4*)&qkv[n * 768 + c];
        float4 k4  = *(const float4*)&qkv[n * 768 + 256 + c];
        float4 v4  = *(const float4*)&qkv[n * 768 + 512 + c];
        float4 pq4 = *(const float4*)&pq[n * 256 + c];
        float4 pk4 = *(const float4*)&pk[n * 256 + c];
        float4 pv4 = *(const float4*)&pv[n * 256 + c];
        int ba = (h * 16 + n) * STA;
        *(float2*)&sA[ba + d]          = make_float2(q4.x, q4.y);
        *(float2*)&sA[ba + d + 2]      = make_float2(q4.z, q4.w);
        *(float2*)&sA[ba + 32 + d]     = make_float2(k4.x, k4.y);
        *(float2*)&sA[ba + 32 + d + 2] = make_float2(k4.z, k4.w);
        *(float2*)&sB[ba + d]          = make_float2(k4.x + pq4.x, k4.y + pq4.y);
        *(float2*)&sB[ba + d + 2]      = make_float2(k4.z + pq4.z, k4.w + pq4.w);
        *(float2*)&sB[ba + 32 + d]     = make_float2(pk4.x, pk4.y);
        *(float2*)&sB[ba + 32 + d + 2] = make_float2(pk4.z, pk4.w);
        int bvi = (h * 16 + n) * STV;
        *(float2*)&sV[bvi + d]          = make_float2(v4.x + pv4.x, v4.y + pv4.y);
        *(float2*)&sV[bvi + d + 2]      = make_float2(v4.z + pv4.z, v4.w + pv4.w);
    }
    __syncthreads();

    int h = t >> 5, l = t & 31;
    int n = l >> 1;
    int mb = (l & 1) * 8;

    ull acc2[8];
#pragma unroll
    for (int j = 0; j < 8; j++) acc2[j] = 0ull;
    const ull* Ar = (const ull*)&sA[(h * 16 + n) * STA];
    const ull* Br[8];
#pragma unroll
    for (int j = 0; j < 8; j++) Br[j] = (const ull*)&sB[(h * 16 + mb + j) * STA];
#pragma unroll 8
    for (int d2 = 0; d2 < 32; d2++) {
        ull a2 = Ar[d2];
#pragma unroll
        for (int j = 0; j < 8; j++) ffma2(acc2[j], a2, Br[j][d2]);
    }
    float dots[8];
#pragma unroll
    for (int j = 0; j < 8; j++) {
        float2 f = unpack2(acc2[j]);
        dots[j] = (f.x + f.y) * SCALE;
    }

    float mx = dots[0];
#pragma unroll
    for (int j = 1; j < 8; j++) mx = fmaxf(mx, dots[j]);
    mx = fmaxf(mx, __shfl_xor_sync(0xFFFFFFFFu, mx, 1));
    float ssum = 0.f, e[8];
#pragma unroll
    for (int j = 0; j < 8; j++) { e[j] = __expf(dots[j] - mx); ssum += e[j]; }
    ssum += __shfl_xor_sync(0xFFFFFFFFu, ssum, 1);
    float inv = 1.f / ssum;
#pragma unroll
    for (int j = 0; j < 8; j++) sAt[(h * 16 + n) * STT + mb + j] = e[j] * inv;
    __syncwarp();

    int dh = (l & 1) * 16;
    ull o2[8];
#pragma unroll
    for (int j = 0; j < 8; j++) o2[j] = 0ull;
    const float* At = &sAt[(h * 16 + n) * STT];
#pragma unroll
    for (int m = 0; m < 16; m++) {
        float a = At[m];
        ull a2 = pack2(a, a);
        const ull* Vr = (const ull*)&sV[(h * 16 + m) * STV + dh];
#pragma unroll
        for (int dp = 0; dp < 8; dp++) ffma2(o2[dp], a2, Vr[dp]);
    }
    float* op = g_attb + (rb + n) * 256 + h * 32 + dh;
#pragma unroll
    for (int dp = 0; dp < 8; dp++) {
        float2 f = unpack2(o2[dp]);
        *(float2*)&op[2 * dp] = f;
    }
}

// ------------------------- host launcher ------------------------------------
extern "C" void kernel_launch(void* const* d_in, const int* in_sizes, int n_in,
                              void* d_out, int out_size) {
    const float* x      = (const float*)d_in[0];
    const float* pr     = (const float*)d_in[1];
    const float* qkv_w  = (const float*)d_in[2];
    const float* proj_w = (const float*)d_in[3];
    const float* proj_b = (const float*)d_in[4];
    const float* q_w1 = (const float*)d_in[5];
    const float* q_g  = (const float*)d_in[7];
    const float* q_be = (const float*)d_in[8];
    const float* q_w2 = (const float*)d_in[9];
    const float* q_b2 = (const float*)d_in[10];
    const float* k_w1 = (const float*)d_in[11];
    const float* k_g  = (const float*)d_in[13];
    const float* k_be = (const float*)d_in[14];
    const float* k_w2 = (const float*)d_in[15];
    const float* k_b2 = (const float*)d_in[16];
    const float* v_w1 = (const float*)d_in[17];
    const float* v_g  = (const float*)d_in[19];
    const float* v_be = (const float*)d_in[20];
    const float* v_w2 = (const float*)d_in[21];
    const float* v_b2 = (const float*)d_in[22];
    float* out = (float*)d_out;

    cudaFuncSetAttribute(mlpA_kernel, cudaFuncAttributeMaxDynamicSharedMemorySize, SMEM_MLPA);
    cudaFuncSetAttribute(gemm_kernel, cudaFuncAttributeMaxDynamicSharedMemorySize, SMEM_GEMM);
    cudaFuncSetAttribute(attn_kernel, cudaFuncAttributeMaxDynamicSharedMemorySize, SMEM_ATT);

    void *p_qkvb = nullptr, *p_attb = nullptr, *p_hbuf = nullptr, *p_pos = nullptr;
    cudaGetSymbolAddress(&p_qkvb, g_qkvb);
    cudaGetSymbolAddress(&p_attb, g_attb);
    cudaGetSymbolAddress(&p_hbuf, g_hbuf);
    cudaGetSymbolAddress(&p_pos,  g_pos);

    float* hbuf = (float*)p_hbuf;
    float* posb = (float*)p_pos;

    stats1_kernel<<<256, 256>>>(pr);
    stats2_kernel<<<10, 256>>>();
    bnfin_kernel<<<1, 768>>>(q_w1, q_g, q_be, k_w1, k_g, k_be, v_w1, v_g, v_be);

    // QKV: (R x 256) @ (768 x 256)^T
    gemm_kernel<<<dim3(2048, 3), 256, SMEM_GEMM>>>(x, qkv_w, nullptr, (float*)p_qkvb, 768);

    // pos-MLP stage A (q,k,v): H = relu(BN(pos @ W1^T))
    mlpA_kernel<<<dim3(2048, 3), 256, SMEM_MLPA>>>(pr, q_w1, k_w1, v_w1);

    // pos-MLP stage B: pos_x = H @ W2^T + b2
    gemm_kernel<<<dim3(2048, 1), 256, SMEM_GEMM>>>(hbuf,                 q_w2, q_b2, posb,                 256);
    gemm_kernel<<<dim3(2048, 1), 256, SMEM_GEMM>>>(hbuf + (long)RWS*256,   k_w2, k_b2, posb + (long)RWS*256,   256);
    gemm_kernel<<<dim3(2048, 1), 256, SMEM_GEMM>>>(hbuf + 2L*RWS*256,      v_w2, v_b2, posb + 2L*RWS*256,      256);

    attn_kernel<<<8192, 256, SMEM_ATT>>>();

    // proj: out = att @ proj_w^T + proj_b
    gemm_kernel<<<dim3(2048, 1), 256, SMEM_GEMM>>>((const float*)p_attb, proj_w, proj_b, out, 256);
}